// round 3
// baseline (speedup 1.0000x reference)
#include <cuda_runtime.h>
#include <cstdint>

#define NMAX 10000
#define EMAX 320000
#define FMAXDIM 768

// ---------------- scratch (static device globals; no allocation) ------------
__device__ int   g_is64;                    // 1 if edge_index is int64
__device__ float g_dinv[NMAX];              // degree, then D^-1/2
__device__ int   g_cnt[NMAX];               // per-target edge counts
__device__ int   g_off[NMAX + 1];           // CSR row offsets (by target)
__device__ int   g_cur[NMAX];               // scatter cursors
__device__ int   g_src[EMAX];               // CSR: source node per edge
__device__ float g_wgt[EMAX];               // CSR: normalized edge weight
__device__ float g_xw[(size_t)NMAX * FMAXDIM];  // GEMM output buffer
__device__ float g_h [(size_t)NMAX * FMAXDIM];  // layer activation buffer

// ---------------- dtype detection -------------------------------------------
// int64 little-endian with values < 2^31 => every odd int32 word is 0.
__global__ void k_detect(const int* __restrict__ ei32, int nwords) {
    // single block, 256 threads; check odd words in the first 2048 words
    __shared__ int any_nonzero;
    if (threadIdx.x == 0) any_nonzero = 0;
    __syncthreads();
    int lim = nwords < 2048 ? nwords : 2048;
    for (int i = threadIdx.x * 2 + 1; i < lim; i += 512)
        if (ei32[i] != 0) atomicOr(&any_nonzero, 1);
    __syncthreads();
    if (threadIdx.x == 0) g_is64 = any_nonzero ? 0 : 1;
}

__device__ __forceinline__ int load_idx(const void* ei, long long pos, int n) {
    int v = g_is64 ? (int)((const long long*)ei)[pos]
                   : ((const int*)ei)[pos];
    // defensive clamp: never form a wild address
    v = v < 0 ? 0 : (v >= n ? n - 1 : v);
    return v;
}

// ---------------- setup kernels ---------------------------------------------
__global__ void k_init(int n) {
    int i = blockIdx.x * blockDim.x + threadIdx.x;
    if (i < n) { g_dinv[i] = 0.0f; g_cnt[i] = 0; }
}

__global__ void k_deg(const void* __restrict__ ei,
                      const float* __restrict__ ew, int E, int n) {
    int e = blockIdx.x * blockDim.x + threadIdx.x;
    if (e >= E) return;
    int c = load_idx(ei, (long long)E + e, n);  // target
    atomicAdd(&g_dinv[c], ew[e]);
    atomicAdd(&g_cnt[c], 1);
}

__global__ void k_dinv(int n) {
    int i = blockIdx.x * blockDim.x + threadIdx.x;
    if (i < n) g_dinv[i] = rsqrtf(g_dinv[i] + 1.0f);  // +1 = self-loop weight
}

// single-block exclusive scan of g_cnt -> g_off, g_cur; g_off[n]=E
__global__ void k_scan(int n) {
    __shared__ int part[1024];
    int t = threadIdx.x;
    int per = (n + 1023) / 1024;
    int base = t * per;
    int s = 0;
    for (int i = 0; i < per; i++) {
        int idx = base + i;
        if (idx < n) s += g_cnt[idx];
    }
    part[t] = s;
    __syncthreads();
    for (int d = 1; d < 1024; d <<= 1) {
        int v = (t >= d) ? part[t - d] : 0;
        __syncthreads();
        part[t] += v;
        __syncthreads();
    }
    int run = (t == 0) ? 0 : part[t - 1];
    for (int i = 0; i < per; i++) {
        int idx = base + i;
        if (idx < n) {
            g_off[idx] = run;
            g_cur[idx] = run;
            run += g_cnt[idx];
        }
    }
    if (t == 1023) g_off[n] = part[1023];
}

__global__ void k_scatter(const void* __restrict__ ei,
                          const float* __restrict__ ew, int E, int n) {
    int e = blockIdx.x * blockDim.x + threadIdx.x;
    if (e >= E) return;
    int r = load_idx(ei, e, n);
    int c = load_idx(ei, (long long)E + e, n);
    int p = atomicAdd(&g_cur[c], 1);
    if (p < EMAX) {
        g_src[p] = r;
        g_wgt[p] = g_dinv[r] * ew[e] * g_dinv[c];
    }
}

// ---------------- fp32 tiled GEMM: C[M,N] = A[M,K] @ B[K,N] -----------------
// BM=128, BN=64, BK=16, 256 threads, 8x4 microtile.
// ASRC: 0 = external ptr, 1 = g_h. C = g_xw.
template <int ASRC>
__global__ void __launch_bounds__(256)
k_gemm(const float* __restrict__ Aext, const float* __restrict__ B,
       int M, int K, int N) {
    const int BM = 128, BN = 64, BK = 16;
    __shared__ float As[BK][BM];
    __shared__ float Bs[BK][BN];
    const float* A = (ASRC == 0) ? Aext : (const float*)g_h;
    float* C = g_xw;
    int tid = threadIdx.x;
    int bm = blockIdx.y * BM, bn = blockIdx.x * BN;
    int tx = tid & 15, ty = tid >> 4;

    float acc[8][4];
#pragma unroll
    for (int i = 0; i < 8; i++)
#pragma unroll
        for (int j = 0; j < 4; j++) acc[i][j] = 0.0f;

    for (int k0 = 0; k0 < K; k0 += BK) {
        // A tile: 128x16, 2 float4 per thread, store transposed
#pragma unroll
        for (int l = 0; l < 2; l++) {
            int id = tid * 2 + l;          // 0..511
            int row = id >> 2;             // 0..127
            int kc = (id & 3) * 4;         // 0,4,8,12
            float4 v = make_float4(0.f, 0.f, 0.f, 0.f);
            int gr = bm + row;
            if (gr < M) v = *(const float4*)(A + (size_t)gr * K + k0 + kc);
            As[kc + 0][row] = v.x;
            As[kc + 1][row] = v.y;
            As[kc + 2][row] = v.z;
            As[kc + 3][row] = v.w;
        }
        // B tile: 16x64, 1 float4 per thread
        {
            int row = tid >> 4;            // 0..15
            int c4 = (tid & 15) * 4;       // 0..60
            float4 v = *(const float4*)(B + (size_t)(k0 + row) * N + bn + c4);
            *(float4*)&Bs[row][c4] = v;
        }
        __syncthreads();
#pragma unroll
        for (int k = 0; k < BK; k++) {
            float ar[8], br[4];
#pragma unroll
            for (int i = 0; i < 8; i++) ar[i] = As[k][ty * 8 + i];
#pragma unroll
            for (int j = 0; j < 4; j++) br[j] = Bs[k][tx * 4 + j];
#pragma unroll
            for (int i = 0; i < 8; i++)
#pragma unroll
                for (int j = 0; j < 4; j++) acc[i][j] += ar[i] * br[j];
        }
        __syncthreads();
    }
#pragma unroll
    for (int i = 0; i < 8; i++) {
        int gr = bm + ty * 8 + i;
        if (gr >= M) continue;
        float4 v = make_float4(acc[i][0], acc[i][1], acc[i][2], acc[i][3]);
        *(float4*)(C + (size_t)gr * N + bn + tx * 4) = v;
    }
}

// ---------------- skinny GEMM for N=8: warp per row (A = g_h, C = g_xw) -----
__global__ void k_gemm8(const float* __restrict__ W, int M, int K) {
    int gw = (blockIdx.x * blockDim.x + threadIdx.x) >> 5;
    int lane = threadIdx.x & 31;
    if (gw >= M) return;
    float acc[8] = {0.f, 0.f, 0.f, 0.f, 0.f, 0.f, 0.f, 0.f};
    const float* a = g_h + (size_t)gw * K;
    for (int k = lane; k < K; k += 32) {
        float av = a[k];
        float4 w0 = *(const float4*)(W + (size_t)k * 8);
        float4 w1 = *(const float4*)(W + (size_t)k * 8 + 4);
        acc[0] += av * w0.x; acc[1] += av * w0.y;
        acc[2] += av * w0.z; acc[3] += av * w0.w;
        acc[4] += av * w1.x; acc[5] += av * w1.y;
        acc[6] += av * w1.z; acc[7] += av * w1.w;
    }
#pragma unroll
    for (int f = 0; f < 8; f++)
#pragma unroll
        for (int o = 16; o > 0; o >>= 1)
            acc[f] += __shfl_down_sync(0xffffffffu, acc[f], o);
    if (lane == 0) {
#pragma unroll
        for (int f = 0; f < 8; f++) g_xw[(size_t)gw * 8 + f] = acc[f];
    }
}

// ---------------- aggregation: warp per node, F in {512,768} ----------------
// reads g_xw, writes g_h, + bias + relu.
template <int F>
__global__ void __launch_bounds__(256)
k_agg(const float* __restrict__ bias, int n) {
    int gw = (blockIdx.x * blockDim.x + threadIdx.x) >> 5;
    int lane = threadIdx.x & 31;
    if (gw >= n) return;
    constexpr int NV = F / 128;  // float4 per lane
    float4 acc[NV];
    float dv = g_dinv[gw];
    float sw = dv * dv;  // self-loop: dinv*1*dinv
    const float4* xr = (const float4*)(g_xw + (size_t)gw * F);
#pragma unroll
    for (int i = 0; i < NV; i++) {
        float4 v = xr[lane + 32 * i];
        acc[i] = make_float4(v.x * sw, v.y * sw, v.z * sw, v.w * sw);
    }
    int s = g_off[gw], e = g_off[gw + 1];
    for (int j = s; j < e; j++) {
        int src = g_src[j];
        float w = g_wgt[j];
        const float4* r = (const float4*)(g_xw + (size_t)src * F);
#pragma unroll
        for (int i = 0; i < NV; i++) {
            float4 v = r[lane + 32 * i];
            acc[i].x += w * v.x;
            acc[i].y += w * v.y;
            acc[i].z += w * v.z;
            acc[i].w += w * v.w;
        }
    }
    const float4* bb = (const float4*)bias;
    float4* op = (float4*)(g_h + (size_t)gw * F);
#pragma unroll
    for (int i = 0; i < NV; i++) {
        float4 b = bb[lane + 32 * i];
        float4 o = make_float4(fmaxf(acc[i].x + b.x, 0.f),
                               fmaxf(acc[i].y + b.y, 0.f),
                               fmaxf(acc[i].z + b.z, 0.f),
                               fmaxf(acc[i].w + b.w, 0.f));
        op[lane + 32 * i] = o;
    }
}

// ---------------- aggregation for F=8: thread per node, writes d_out --------
__global__ void k_agg8(const float* __restrict__ bias, float* __restrict__ out,
                       int n) {
    int v = blockIdx.x * blockDim.x + threadIdx.x;
    if (v >= n) return;
    float dv = g_dinv[v];
    float sw = dv * dv;
    float acc[8];
    const float* xr = g_xw + (size_t)v * 8;
#pragma unroll
    for (int f = 0; f < 8; f++) acc[f] = xr[f] * sw;
    int s = g_off[v], e = g_off[v + 1];
    for (int j = s; j < e; j++) {
        int src = g_src[j];
        float w = g_wgt[j];
        const float* r = g_xw + (size_t)src * 8;
#pragma unroll
        for (int f = 0; f < 8; f++) acc[f] += w * r[f];
    }
#pragma unroll
    for (int f = 0; f < 8; f++) out[(size_t)v * 8 + f] = acc[f] + bias[f];
}

// ---------------- launch ----------------------------------------------------
extern "C" void kernel_launch(void* const* d_in, const int* in_sizes, int n_in,
                              void* d_out, int out_size) {
    const float* x  = (const float*)d_in[0];
    const void*  ei = d_in[1];
    const float* ew = (const float*)d_in[2];
    const float* W1 = (const float*)d_in[3];
    const float* b1 = (const float*)d_in[4];
    const float* W2 = (const float*)d_in[5];
    const float* b2 = (const float*)d_in[6];
    const float* W3 = (const float*)d_in[7];
    const float* b3 = (const float*)d_in[8];
    float* out = (float*)d_out;

    int N = in_sizes[0] / 256;
    int E = in_sizes[2];

    // ---- dtype sniff + normalization + CSR build ----
    k_detect<<<1, 256>>>((const int*)ei, in_sizes[1]);
    k_init<<<(N + 255) / 256, 256>>>(N);
    k_deg<<<(E + 255) / 256, 256>>>(ei, ew, E, N);
    k_dinv<<<(N + 255) / 256, 256>>>(N);
    k_scan<<<1, 1024>>>(N);
    k_scatter<<<(E + 255) / 256, 256>>>(ei, ew, E, N);

    // ---- layer 1: [N,256]@[256,512] -> g_xw, aggregate+bias+relu -> g_h ----
    k_gemm<0><<<dim3(512 / 64, (N + 127) / 128), 256>>>(x, W1, N, 256, 512);
    k_agg<512><<<(N * 32 + 255) / 256, 256>>>(b1, N);

    // ---- layer 2: [N,512]@[512,768] -> g_xw, aggregate+bias+relu -> g_h ----
    k_gemm<1><<<dim3(768 / 64, (N + 127) / 128), 256>>>(nullptr, W2, N, 512, 768);
    k_agg<768><<<(N * 32 + 255) / 256, 256>>>(b2, N);

    // ---- layer 3: [N,768]@[768,8] -> g_xw, aggregate+bias -> out ----
    k_gemm8<<<(N * 32 + 255) / 256, 256>>>(W3, N, 768);
    k_agg8<<<(N + 255) / 256, 256>>>(b3, out, N);
}

// round 5
// speedup vs baseline: 1.6420x; 1.6420x over previous
#include <cuda_runtime.h>
#include <cstdint>

#define NMAX 10000
#define EMAX 320000

// ---------------- scratch (static device globals; no allocation) ------------
__device__ int   g_is64;                    // 1 if edge_index is int64
__device__ float g_dinv[NMAX];              // degree, then D^-1/2
__device__ int   g_cnt[NMAX];               // per-target edge counts
__device__ int   g_off[NMAX + 1];           // CSR row offsets (by target)
__device__ int   g_cur[NMAX];               // scatter cursors
__device__ int   g_src[EMAX];               // CSR: source node per edge
__device__ float g_wgt[EMAX];               // CSR: normalized edge weight
__device__ float g_a [(size_t)NMAX * 512];  // aggregation output (pre-GEMM)
__device__ float g_h [(size_t)NMAX * 768];  // layer activation (post-GEMM)
__device__ float g_o8[(size_t)NMAX * 8];    // layer-3 GEMM output

// ---------------- dtype detection -------------------------------------------
__global__ void k_detect(const int* __restrict__ ei32, int nwords) {
    __shared__ int any_nonzero;
    if (threadIdx.x == 0) any_nonzero = 0;
    __syncthreads();
    int lim = nwords < 2048 ? nwords : 2048;
    for (int i = threadIdx.x * 2 + 1; i < lim; i += 512)
        if (ei32[i] != 0) atomicOr(&any_nonzero, 1);
    __syncthreads();
    if (threadIdx.x == 0) g_is64 = any_nonzero ? 0 : 1;
}

__device__ __forceinline__ int load_idx(const void* ei, long long pos, int n) {
    int v = g_is64 ? (int)((const long long*)ei)[pos]
                   : ((const int*)ei)[pos];
    v = v < 0 ? 0 : (v >= n ? n - 1 : v);
    return v;
}

// ---------------- setup kernels ---------------------------------------------
__global__ void k_init(int n) {
    int i = blockIdx.x * blockDim.x + threadIdx.x;
    if (i < n) { g_dinv[i] = 0.0f; g_cnt[i] = 0; }
}

__global__ void k_deg(const void* __restrict__ ei,
                      const float* __restrict__ ew, int E, int n) {
    int e = blockIdx.x * blockDim.x + threadIdx.x;
    if (e >= E) return;
    int c = load_idx(ei, (long long)E + e, n);
    atomicAdd(&g_dinv[c], ew[e]);
    atomicAdd(&g_cnt[c], 1);
}

__global__ void k_dinv(int n) {
    int i = blockIdx.x * blockDim.x + threadIdx.x;
    if (i < n) g_dinv[i] = rsqrtf(g_dinv[i] + 1.0f);
}

__global__ void k_scan(int n) {
    __shared__ int part[1024];
    int t = threadIdx.x;
    int per = (n + 1023) / 1024;
    int base = t * per;
    int s = 0;
    for (int i = 0; i < per; i++) {
        int idx = base + i;
        if (idx < n) s += g_cnt[idx];
    }
    part[t] = s;
    __syncthreads();
    for (int d = 1; d < 1024; d <<= 1) {
        int v = (t >= d) ? part[t - d] : 0;
        __syncthreads();
        part[t] += v;
        __syncthreads();
    }
    int run = (t == 0) ? 0 : part[t - 1];
    for (int i = 0; i < per; i++) {
        int idx = base + i;
        if (idx < n) {
            g_off[idx] = run;
            g_cur[idx] = run;
            run += g_cnt[idx];
        }
    }
    if (t == 1023) g_off[n] = part[1023];
}

__global__ void k_scatter(const void* __restrict__ ei,
                          const float* __restrict__ ew, int E, int n) {
    int e = blockIdx.x * blockDim.x + threadIdx.x;
    if (e >= E) return;
    int r = load_idx(ei, e, n);
    int c = load_idx(ei, (long long)E + e, n);
    int p = atomicAdd(&g_cur[c], 1);
    if (p < EMAX) {
        g_src[p] = r;
        g_wgt[p] = g_dinv[r] * ew[e] * g_dinv[c];
    }
}

// ---------------- tf32 helpers ----------------------------------------------
__device__ __forceinline__ uint32_t f2tf32(float f) {
    uint32_t r;
    asm("cvt.rna.tf32.f32 %0, %1;" : "=r"(r) : "f"(f));
    return r;
}

// ---------------- TF32 tensor-core GEMM: C = relu(A@B + bias) ---------------
// A = g_a [M,K] row-major, B [K,N] row-major, C = g_h [M,N].
// BM=128, BN=64, BK=16, 256 threads (8 warps, 4x2 warp grid, 32x32 warp tile).
__global__ void __launch_bounds__(256)
k_gemm_tf32(const float* __restrict__ B, const float* __restrict__ bias,
            int M, int K, int N) {
    __shared__ uint32_t As[16][136];  // [k][m], padded stride -> conflict-free
    __shared__ uint32_t Bs[16][72];   // [k][n]
    const float* A = g_a;
    float* C = g_h;
    int tid = threadIdx.x;
    int lane = tid & 31, wid = tid >> 5;
    int wm = wid >> 1, wn = wid & 1;          // warp coords: 4x2
    int bm = blockIdx.y * 128, bn = blockIdx.x * 64;

    float acc[2][4][4];
#pragma unroll
    for (int i = 0; i < 2; i++)
#pragma unroll
        for (int j = 0; j < 4; j++)
#pragma unroll
            for (int r = 0; r < 4; r++) acc[i][j][r] = 0.0f;

    for (int k0 = 0; k0 < K; k0 += 16) {
        // A tile 128x16: 2 float4 per thread, stored transposed [k][m]
#pragma unroll
        for (int l = 0; l < 2; l++) {
            int id = tid * 2 + l;
            int row = id >> 2;
            int kc = (id & 3) * 4;
            float4 v = make_float4(0.f, 0.f, 0.f, 0.f);
            int gr = bm + row;
            if (gr < M) v = *(const float4*)(A + (size_t)gr * K + k0 + kc);
            As[kc + 0][row] = f2tf32(v.x);
            As[kc + 1][row] = f2tf32(v.y);
            As[kc + 2][row] = f2tf32(v.z);
            As[kc + 3][row] = f2tf32(v.w);
        }
        // B tile 16x64: 1 float4 per thread
        {
            int row = tid >> 4;
            int c4 = (tid & 15) * 4;
            float4 v = *(const float4*)(B + (size_t)(k0 + row) * N + bn + c4);
            Bs[row][c4 + 0] = f2tf32(v.x);
            Bs[row][c4 + 1] = f2tf32(v.y);
            Bs[row][c4 + 2] = f2tf32(v.z);
            Bs[row][c4 + 3] = f2tf32(v.w);
        }
        __syncthreads();

#pragma unroll
        for (int ks = 0; ks < 2; ks++) {
            int kk = ks * 8;
            uint32_t a[2][4], b[4][2];
            // PTX m16n8k8 A fragment order:
            //   a0=A[r][k], a1=A[r+8][k], a2=A[r][k+4], a3=A[r+8][k+4]
#pragma unroll
            for (int i = 0; i < 2; i++) {
                int m = wm * 32 + i * 16 + (lane >> 2);
                a[i][0] = As[kk + (lane & 3)    ][m];
                a[i][1] = As[kk + (lane & 3)    ][m + 8];
                a[i][2] = As[kk + (lane & 3) + 4][m];
                a[i][3] = As[kk + (lane & 3) + 4][m + 8];
            }
#pragma unroll
            for (int j = 0; j < 4; j++) {
                int nn = wn * 32 + j * 8 + (lane >> 2);
                b[j][0] = Bs[kk + (lane & 3)    ][nn];
                b[j][1] = Bs[kk + (lane & 3) + 4][nn];
            }
#pragma unroll
            for (int i = 0; i < 2; i++)
#pragma unroll
                for (int j = 0; j < 4; j++) {
                    asm volatile(
                        "mma.sync.aligned.m16n8k8.row.col.f32.tf32.tf32.f32 "
                        "{%0,%1,%2,%3}, {%4,%5,%6,%7}, {%8,%9}, {%0,%1,%2,%3};\n"
                        : "+f"(acc[i][j][0]), "+f"(acc[i][j][1]),
                          "+f"(acc[i][j][2]), "+f"(acc[i][j][3])
                        : "r"(a[i][0]), "r"(a[i][1]), "r"(a[i][2]), "r"(a[i][3]),
                          "r"(b[j][0]), "r"(b[j][1]));
                }
        }
        __syncthreads();
    }

    // epilogue: bias + relu, c0/c1 at (row, col..col+1), c2/c3 at (row+8, ..)
#pragma unroll
    for (int i = 0; i < 2; i++) {
#pragma unroll
        for (int j = 0; j < 4; j++) {
            int row = bm + wm * 32 + i * 16 + (lane >> 2);
            int col = bn + wn * 32 + j * 8 + (lane & 3) * 2;
            float b0 = bias[col], b1 = bias[col + 1];
            if (row < M) {
                float2 v0 = make_float2(fmaxf(acc[i][j][0] + b0, 0.f),
                                        fmaxf(acc[i][j][1] + b1, 0.f));
                *(float2*)(C + (size_t)row * N + col) = v0;
            }
            if (row + 8 < M) {
                float2 v1 = make_float2(fmaxf(acc[i][j][2] + b0, 0.f),
                                        fmaxf(acc[i][j][3] + b1, 0.f));
                *(float2*)(C + (size_t)(row + 8) * N + col) = v1;
            }
        }
    }
}

// ---------------- skinny GEMM for N=8: warp per row (A = g_h, C = g_o8) -----
__global__ void k_gemm8(const float* __restrict__ W, int M, int K) {
    int gw = (blockIdx.x * blockDim.x + threadIdx.x) >> 5;
    int lane = threadIdx.x & 31;
    if (gw >= M) return;
    float acc[8] = {0.f, 0.f, 0.f, 0.f, 0.f, 0.f, 0.f, 0.f};
    const float* a = g_h + (size_t)gw * K;
    for (int k = lane; k < K; k += 32) {
        float av = a[k];
        float4 w0 = *(const float4*)(W + (size_t)k * 8);
        float4 w1 = *(const float4*)(W + (size_t)k * 8 + 4);
        acc[0] += av * w0.x; acc[1] += av * w0.y;
        acc[2] += av * w0.z; acc[3] += av * w0.w;
        acc[4] += av * w1.x; acc[5] += av * w1.y;
        acc[6] += av * w1.z; acc[7] += av * w1.w;
    }
#pragma unroll
    for (int f = 0; f < 8; f++)
#pragma unroll
        for (int o = 16; o > 0; o >>= 1)
            acc[f] += __shfl_down_sync(0xffffffffu, acc[f], o);
    if (lane == 0) {
#pragma unroll
        for (int f = 0; f < 8; f++) g_o8[(size_t)gw * 8 + f] = acc[f];
    }
}

// ---------------- aggregation (pre-GEMM): warp per node ---------------------
// out = A_norm @ X. No bias/relu. ASRC: 0 = external ptr, 1 = g_h. Writes g_a.
template <int F, int ASRC>
__global__ void __launch_bounds__(256)
k_agg(const float* __restrict__ Xext, int n) {
    int gw = (blockIdx.x * blockDim.x + threadIdx.x) >> 5;
    int lane = threadIdx.x & 31;
    if (gw >= n) return;
    const float* X = (ASRC == 0) ? Xext : (const float*)g_h;
    constexpr int NV = F / 128;  // float4 per lane
    float4 acc[NV];
    float dv = g_dinv[gw];
    float sw = dv * dv;  // self-loop term
    const float4* xr = (const float4*)(X + (size_t)gw * F);
#pragma unroll
    for (int i = 0; i < NV; i++) {
        float4 v = xr[lane + 32 * i];
        acc[i] = make_float4(v.x * sw, v.y * sw, v.z * sw, v.w * sw);
    }
    int s = g_off[gw], e = g_off[gw + 1];
    for (int j = s; j < e; j++) {
        int src = g_src[j];
        float w = g_wgt[j];
        const float4* r = (const float4*)(X + (size_t)src * F);
#pragma unroll
        for (int i = 0; i < NV; i++) {
            float4 v = r[lane + 32 * i];
            acc[i].x += w * v.x;
            acc[i].y += w * v.y;
            acc[i].z += w * v.z;
            acc[i].w += w * v.w;
        }
    }
    float4* op = (float4*)(g_a + (size_t)gw * F);
#pragma unroll
    for (int i = 0; i < NV; i++) op[lane + 32 * i] = acc[i];
}

// ---------------- aggregation for F=8 (+bias), writes d_out -----------------
__global__ void k_agg8(const float* __restrict__ bias, float* __restrict__ out,
                       int n) {
    int v = blockIdx.x * blockDim.x + threadIdx.x;
    if (v >= n) return;
    float dv = g_dinv[v];
    float sw = dv * dv;
    float acc[8];
    const float* xr = g_o8 + (size_t)v * 8;
#pragma unroll
    for (int f = 0; f < 8; f++) acc[f] = xr[f] * sw;
    int s = g_off[v], e = g_off[v + 1];
    for (int j = s; j < e; j++) {
        int src = g_src[j];
        float w = g_wgt[j];
        const float* r = g_o8 + (size_t)src * 8;
#pragma unroll
        for (int f = 0; f < 8; f++) acc[f] += w * r[f];
    }
#pragma unroll
    for (int f = 0; f < 8; f++) out[(size_t)v * 8 + f] = acc[f] + bias[f];
}

// ---------------- launch ----------------------------------------------------
extern "C" void kernel_launch(void* const* d_in, const int* in_sizes, int n_in,
                              void* d_out, int out_size) {
    const float* x  = (const float*)d_in[0];
    const void*  ei = d_in[1];
    const float* ew = (const float*)d_in[2];
    const float* W1 = (const float*)d_in[3];
    const float* b1 = (const float*)d_in[4];
    const float* W2 = (const float*)d_in[5];
    const float* b2 = (const float*)d_in[6];
    const float* W3 = (const float*)d_in[7];
    const float* b3 = (const float*)d_in[8];
    float* out = (float*)d_out;

    int N = in_sizes[0] / 256;
    int E = in_sizes[2];

    // ---- dtype sniff + normalization + CSR build ----
    k_detect<<<1, 256>>>((const int*)ei, in_sizes[1]);
    k_init<<<(N + 255) / 256, 256>>>(N);
    k_deg<<<(E + 255) / 256, 256>>>(ei, ew, E, N);
    k_dinv<<<(N + 255) / 256, 256>>>(N);
    k_scan<<<1, 1024>>>(N);
    k_scatter<<<(E + 255) / 256, 256>>>(ei, ew, E, N);

    // ---- layer 1: agg(x) @ 256 -> g_a, then relu(g_a@W1+b1) -> g_h ----
    k_agg<256, 0><<<(N * 32 + 255) / 256, 256>>>(x, N);
    k_gemm_tf32<<<dim3(512 / 64, (N + 127) / 128), 256>>>(W1, b1, N, 256, 512);

    // ---- layer 2: agg(g_h) @ 512 -> g_a, then relu(g_a@W2+b2) -> g_h ----
    k_agg<512, 1><<<(N * 32 + 255) / 256, 256>>>(nullptr, N);
    k_gemm_tf32<<<dim3(768 / 64, (N + 127) / 128), 256>>>(W2, b2, N, 512, 768);

    // ---- layer 3: g_h@W3 -> g_o8 (8 wide), then agg + bias -> out ----
    k_gemm8<<<(N * 32 + 255) / 256, 256>>>(W3, N, 768);
    k_agg8<<<(N + 255) / 256, 256>>>(b3, out, N);
}

// round 6
// speedup vs baseline: 1.8388x; 1.1198x over previous
#include <cuda_runtime.h>
#include <cstdint>

#define NMAX 10000
#define EMAX 320000

// ---------------- scratch (static device globals; no allocation) ------------
__device__ int   g_is64;
__device__ float g_dinv[NMAX];
__device__ int   g_cnt[NMAX];
__device__ int   g_off[NMAX + 1];
__device__ int   g_cur[NMAX];
__device__ int   g_src[EMAX];
__device__ float g_wgt[EMAX];
__device__ float g_a [(size_t)NMAX * 512];  // aggregation output (pre-GEMM)
__device__ float g_h [(size_t)NMAX * 768];  // layer activation (post-GEMM)
__device__ float g_o8[(size_t)NMAX * 8];    // layer-3 GEMM output

// ---------------- fused init + dtype detect ---------------------------------
__global__ void k_init_detect(const int* __restrict__ ei32, int nwords, int n) {
    int i = blockIdx.x * blockDim.x + threadIdx.x;
    if (i < n) { g_dinv[i] = 0.0f; g_cnt[i] = 0; }
    if (blockIdx.x == 0) {
        __shared__ int any_nonzero;
        if (threadIdx.x == 0) any_nonzero = 0;
        __syncthreads();
        int lim = nwords < 2048 ? nwords : 2048;
        for (int w = threadIdx.x * 2 + 1; w < lim; w += 512)
            if (ei32[w] != 0) atomicOr(&any_nonzero, 1);
        __syncthreads();
        if (threadIdx.x == 0) g_is64 = any_nonzero ? 0 : 1;
    }
}

__device__ __forceinline__ int load_idx(const void* ei, long long pos, int n) {
    int v = g_is64 ? (int)((const long long*)ei)[pos]
                   : ((const int*)ei)[pos];
    v = v < 0 ? 0 : (v >= n ? n - 1 : v);
    return v;
}

__global__ void k_deg(const void* __restrict__ ei,
                      const float* __restrict__ ew, int E, int n) {
    int e = blockIdx.x * blockDim.x + threadIdx.x;
    if (e >= E) return;
    int c = load_idx(ei, (long long)E + e, n);
    atomicAdd(&g_dinv[c], ew[e]);
    atomicAdd(&g_cnt[c], 1);
}

// scan (single block) + fold in dinv computation
__global__ void k_scan(int n) {
    __shared__ int part[1024];
    int t = threadIdx.x;
    // dinv first (elementwise, independent of the count scan)
    for (int i = t; i < n; i += 1024)
        g_dinv[i] = rsqrtf(g_dinv[i] + 1.0f);
    int per = (n + 1023) / 1024;
    int base = t * per;
    int s = 0;
    for (int i = 0; i < per; i++) {
        int idx = base + i;
        if (idx < n) s += g_cnt[idx];
    }
    part[t] = s;
    __syncthreads();
    for (int d = 1; d < 1024; d <<= 1) {
        int v = (t >= d) ? part[t - d] : 0;
        __syncthreads();
        part[t] += v;
        __syncthreads();
    }
    int run = (t == 0) ? 0 : part[t - 1];
    for (int i = 0; i < per; i++) {
        int idx = base + i;
        if (idx < n) {
            g_off[idx] = run;
            g_cur[idx] = run;
            run += g_cnt[idx];
        }
    }
    if (t == 1023) g_off[n] = part[1023];
}

__global__ void k_scatter(const void* __restrict__ ei,
                          const float* __restrict__ ew, int E, int n) {
    int e = blockIdx.x * blockDim.x + threadIdx.x;
    if (e >= E) return;
    int r = load_idx(ei, e, n);
    int c = load_idx(ei, (long long)E + e, n);
    int p = atomicAdd(&g_cur[c], 1);
    if (p < EMAX) {
        g_src[p] = r;
        g_wgt[p] = g_dinv[r] * ew[e] * g_dinv[c];
    }
}

// ---------------- helpers ----------------------------------------------------
__device__ __forceinline__ uint32_t f2tf32(float f) {
    uint32_t r;
    asm("cvt.rna.tf32.f32 %0, %1;" : "=r"(r) : "f"(f));
    return r;
}

__device__ __forceinline__ void cp_async16(uint32_t smem_addr, const void* gptr,
                                           int src_bytes) {
    asm volatile("cp.async.cg.shared.global [%0], [%1], 16, %2;"
                 :: "r"(smem_addr), "l"(gptr), "r"(src_bytes));
}
__device__ __forceinline__ void cp_commit() {
    asm volatile("cp.async.commit_group;");
}
__device__ __forceinline__ void cp_wait1() {
    asm volatile("cp.async.wait_group 1;");
}

// ---------------- TF32 TC GEMM, cp.async double-buffered --------------------
// C = relu(A@B + bias); A = g_a [M,K], B [K,N], C = g_h.
// BM=128, BN=64, BK=16, 256 threads, 8 warps (4x2), 32x32 warp tile.
__global__ void __launch_bounds__(256)
k_gemm_tf32(const float* __restrict__ B, const float* __restrict__ bias,
            int M, int K, int N) {
    __shared__ float As[2][128][20];  // [stage][m][k], stride 20 -> cf frags
    __shared__ float Bs[2][16][72];   // [stage][k][n], stride 72 -> cf frags
    const float* A = g_a;
    float* C = g_h;
    int tid = threadIdx.x;
    int lane = tid & 31, wid = tid >> 5;
    int wm = wid >> 1, wn = wid & 1;
    int bm = blockIdx.y * 128, bn = blockIdx.x * 64;

    // per-thread cp.async coords
    int a_row = tid >> 1;              // 0..127 (2 chunks per thread, same row)
    int a_col0 = (tid & 1) * 8;        // 0 or 8; chunks at col0, col0+4
    int b_row = tid >> 4;              // 0..15
    int b_col = (tid & 15) * 4;        // 0..60

    const float* a_src_base = A + (size_t)(bm + a_row) * K + a_col0;
    int a_valid = (bm + a_row) < M ? 16 : 0;
    const float* b_src_base = B + (size_t)b_row * N + bn + b_col;

    uint32_t as_base = (uint32_t)__cvta_generic_to_shared(&As[0][0][0]);
    uint32_t bs_base = (uint32_t)__cvta_generic_to_shared(&Bs[0][0][0]);
    uint32_t as_stage_sz = 128 * 20 * 4;
    uint32_t bs_stage_sz = 16 * 72 * 4;

    auto load_tile = [&](int stage, int k0) {
        uint32_t ad = as_base + stage * as_stage_sz + (a_row * 20 + a_col0) * 4;
        cp_async16(ad, a_src_base + k0, a_valid);
        cp_async16(ad + 16, a_src_base + k0 + 4, a_valid);
        uint32_t bd = bs_base + stage * bs_stage_sz + (b_row * 72 + b_col) * 4;
        cp_async16(bd, b_src_base + (size_t)k0 * N, 16);
    };

    float acc[2][4][4];
#pragma unroll
    for (int i = 0; i < 2; i++)
#pragma unroll
        for (int j = 0; j < 4; j++)
#pragma unroll
            for (int r = 0; r < 4; r++) acc[i][j][r] = 0.0f;

    int nIters = K >> 4;
    load_tile(0, 0);
    cp_commit();

    for (int it = 0; it < nIters; it++) {
        if (it + 1 < nIters) load_tile((it + 1) & 1, (it + 1) << 4);
        cp_commit();
        cp_wait1();
        __syncthreads();
        int st = it & 1;

#pragma unroll
        for (int ks = 0; ks < 2; ks++) {
            int kk = ks * 8 + (lane & 3);
            uint32_t a[2][4], b[4][2];
#pragma unroll
            for (int i = 0; i < 2; i++) {
                int m = wm * 32 + i * 16 + (lane >> 2);
                a[i][0] = f2tf32(As[st][m    ][kk]);
                a[i][1] = f2tf32(As[st][m + 8][kk]);
                a[i][2] = f2tf32(As[st][m    ][kk + 4]);
                a[i][3] = f2tf32(As[st][m + 8][kk + 4]);
            }
#pragma unroll
            for (int j = 0; j < 4; j++) {
                int nn = wn * 32 + j * 8 + (lane >> 2);
                b[j][0] = f2tf32(Bs[st][kk    ][nn]);
                b[j][1] = f2tf32(Bs[st][kk + 4][nn]);
            }
#pragma unroll
            for (int i = 0; i < 2; i++)
#pragma unroll
                for (int j = 0; j < 4; j++) {
                    asm volatile(
                        "mma.sync.aligned.m16n8k8.row.col.f32.tf32.tf32.f32 "
                        "{%0,%1,%2,%3}, {%4,%5,%6,%7}, {%8,%9}, {%0,%1,%2,%3};\n"
                        : "+f"(acc[i][j][0]), "+f"(acc[i][j][1]),
                          "+f"(acc[i][j][2]), "+f"(acc[i][j][3])
                        : "r"(a[i][0]), "r"(a[i][1]), "r"(a[i][2]), "r"(a[i][3]),
                          "r"(b[j][0]), "r"(b[j][1]));
                }
        }
        __syncthreads();
    }

    // epilogue: bias + relu
#pragma unroll
    for (int i = 0; i < 2; i++) {
#pragma unroll
        for (int j = 0; j < 4; j++) {
            int row = bm + wm * 32 + i * 16 + (lane >> 2);
            int col = bn + wn * 32 + j * 8 + (lane & 3) * 2;
            float b0 = __ldg(bias + col), b1 = __ldg(bias + col + 1);
            if (row < M) {
                float2 v0 = make_float2(fmaxf(acc[i][j][0] + b0, 0.f),
                                        fmaxf(acc[i][j][1] + b1, 0.f));
                *(float2*)(C + (size_t)row * N + col) = v0;
            }
            if (row + 8 < M) {
                float2 v1 = make_float2(fmaxf(acc[i][j][2] + b0, 0.f),
                                        fmaxf(acc[i][j][3] + b1, 0.f));
                *(float2*)(C + (size_t)(row + 8) * N + col) = v1;
            }
        }
    }
}

// ---------------- skinny GEMM for N=8: warp per row -------------------------
__global__ void k_gemm8(const float* __restrict__ W, int M, int K) {
    int gw = (blockIdx.x * blockDim.x + threadIdx.x) >> 5;
    int lane = threadIdx.x & 31;
    if (gw >= M) return;
    float acc[8] = {0.f, 0.f, 0.f, 0.f, 0.f, 0.f, 0.f, 0.f};
    const float* a = g_h + (size_t)gw * K;
    for (int k = lane; k < K; k += 32) {
        float av = a[k];
        float4 w0 = *(const float4*)(W + (size_t)k * 8);
        float4 w1 = *(const float4*)(W + (size_t)k * 8 + 4);
        acc[0] += av * w0.x; acc[1] += av * w0.y;
        acc[2] += av * w0.z; acc[3] += av * w0.w;
        acc[4] += av * w1.x; acc[5] += av * w1.y;
        acc[6] += av * w1.z; acc[7] += av * w1.w;
    }
#pragma unroll
    for (int f = 0; f < 8; f++)
#pragma unroll
        for (int o = 16; o > 0; o >>= 1)
            acc[f] += __shfl_down_sync(0xffffffffu, acc[f], o);
    if (lane == 0) {
#pragma unroll
        for (int f = 0; f < 8; f++) g_o8[(size_t)gw * 8 + f] = acc[f];
    }
}

// ---------------- aggregation (pre-GEMM): warp per node, x2 unroll ----------
template <int F, int ASRC>
__global__ void __launch_bounds__(256)
k_agg(const float* __restrict__ Xext, int n) {
    int gw = (blockIdx.x * blockDim.x + threadIdx.x) >> 5;
    int lane = threadIdx.x & 31;
    if (gw >= n) return;
    const float* X = (ASRC == 0) ? Xext : (const float*)g_h;
    constexpr int NV = F / 128;
    float4 acc[NV];
    float dv = g_dinv[gw];
    float sw = dv * dv;
    const float4* xr = (const float4*)(X + (size_t)gw * F);
#pragma unroll
    for (int i = 0; i < NV; i++) {
        float4 v = xr[lane + 32 * i];
        acc[i] = make_float4(v.x * sw, v.y * sw, v.z * sw, v.w * sw);
    }
    int s = g_off[gw], e = g_off[gw + 1];
    int j = s;
    for (; j + 1 < e; j += 2) {
        int s0 = g_src[j], s1 = g_src[j + 1];
        float w0 = g_wgt[j], w1 = g_wgt[j + 1];
        const float4* r0 = (const float4*)(X + (size_t)s0 * F);
        const float4* r1 = (const float4*)(X + (size_t)s1 * F);
#pragma unroll
        for (int i = 0; i < NV; i++) {
            float4 v0 = r0[lane + 32 * i];
            float4 v1 = r1[lane + 32 * i];
            acc[i].x += w0 * v0.x + w1 * v1.x;
            acc[i].y += w0 * v0.y + w1 * v1.y;
            acc[i].z += w0 * v0.z + w1 * v1.z;
            acc[i].w += w0 * v0.w + w1 * v1.w;
        }
    }
    if (j < e) {
        int s0 = g_src[j];
        float w0 = g_wgt[j];
        const float4* r0 = (const float4*)(X + (size_t)s0 * F);
#pragma unroll
        for (int i = 0; i < NV; i++) {
            float4 v0 = r0[lane + 32 * i];
            acc[i].x += w0 * v0.x;
            acc[i].y += w0 * v0.y;
            acc[i].z += w0 * v0.z;
            acc[i].w += w0 * v0.w;
        }
    }
    float4* op = (float4*)(g_a + (size_t)gw * F);
#pragma unroll
    for (int i = 0; i < NV; i++) op[lane + 32 * i] = acc[i];
}

// ---------------- aggregation for F=8 (+bias), writes d_out -----------------
__global__ void k_agg8(const float* __restrict__ bias, float* __restrict__ out,
                       int n) {
    int v = blockIdx.x * blockDim.x + threadIdx.x;
    if (v >= n) return;
    float dv = g_dinv[v];
    float sw = dv * dv;
    float acc[8];
    const float* xr = g_o8 + (size_t)v * 8;
#pragma unroll
    for (int f = 0; f < 8; f++) acc[f] = xr[f] * sw;
    int s = g_off[v], e = g_off[v + 1];
    for (int j = s; j < e; j++) {
        int src = g_src[j];
        float w = g_wgt[j];
        const float* r = g_o8 + (size_t)src * 8;
#pragma unroll
        for (int f = 0; f < 8; f++) acc[f] += w * r[f];
    }
#pragma unroll
    for (int f = 0; f < 8; f++) out[(size_t)v * 8 + f] = acc[f] + bias[f];
}

// ---------------- launch ----------------------------------------------------
extern "C" void kernel_launch(void* const* d_in, const int* in_sizes, int n_in,
                              void* d_out, int out_size) {
    const float* x  = (const float*)d_in[0];
    const void*  ei = d_in[1];
    const float* ew = (const float*)d_in[2];
    const float* W1 = (const float*)d_in[3];
    const float* b1 = (const float*)d_in[4];
    const float* W2 = (const float*)d_in[5];
    const float* b2 = (const float*)d_in[6];
    const float* W3 = (const float*)d_in[7];
    const float* b3 = (const float*)d_in[8];
    float* out = (float*)d_out;

    int N = in_sizes[0] / 256;
    int E = in_sizes[2];

    // ---- setup: init+detect, degree, scan+dinv, scatter ----
    k_init_detect<<<(N + 255) / 256, 256>>>((const int*)ei, in_sizes[1], N);
    k_deg<<<(E + 255) / 256, 256>>>(ei, ew, E, N);
    k_scan<<<1, 1024>>>(N);
    k_scatter<<<(E + 255) / 256, 256>>>(ei, ew, E, N);

    // ---- layer 1: agg(x)@256 -> g_a; relu(g_a@W1+b1) -> g_h ----
    k_agg<256, 0><<<(N * 32 + 255) / 256, 256>>>(x, N);
    k_gemm_tf32<<<dim3(512 / 64, (N + 127) / 128), 256>>>(W1, b1, N, 256, 512);

    // ---- layer 2: agg(g_h)@512 -> g_a; relu(g_a@W2+b2) -> g_h ----
    k_agg<512, 1><<<(N * 32 + 255) / 256, 256>>>(nullptr, N);
    k_gemm_tf32<<<dim3(768 / 64, (N + 127) / 128), 256>>>(W2, b2, N, 512, 768);

    // ---- layer 3: g_h@W3 -> g_o8; agg + bias -> out ----
    k_gemm8<<<(N * 32 + 255) / 256, 256>>>(W3, N, 768);
    k_agg8<<<(N + 255) / 256, 256>>>(b3, out, N);
}